// round 9
// baseline (speedup 1.0000x reference)
#include <cuda_runtime.h>
#include <math.h>

#define DIM   768
#define D3    2304
#define BATCH 8
#define SLEN  256
#define TLEN  128
#define VOC   50257
#define NHEAD 12
#define HDIM  64
#define NBLK  96

// ---------------- scratch (device globals; no allocation) ----------------
__device__ float g_buf[17301504];          // ~66 MB
__device__ float g_h[2][BATCH * DIM];      // GRU hidden ping-pong
__device__ float g_henc[BATCH * DIM];
__device__ unsigned long long g_best[1024];
__device__ double g_part[512];
__device__ unsigned g_cnt = 0;
__device__ unsigned g_gen = 0;

// g_buf offsets (floats)
#define OFF_SRC_E  0u
#define OFF_DST_E  1572864u
#define OFF_GI     2359296u
#define OFF_FINAL  7077888u
#define OFF_CAND   7864320u
#define OFF_Q      8650752u
#define OFF_KP     10223616u
#define OFF_VP     11010048u
#define OFF_AO     11796480u
#define OFF_COUT   13369344u
#define OFF_CAFT   14942208u
#define OFF_DSTOUT 16515072u

__device__ __forceinline__ float sigm(float x) { return 1.0f / (1.0f + expf(-x)); }

// Grid barrier for NBLK co-resident blocks. Generation-based; g_gen grows
// monotonically across the whole run (relative compares only -> deterministic).
__device__ __forceinline__ void gbar(unsigned& gen) {
    __syncthreads();
    if (threadIdx.x == 0) {
        __threadfence();
        unsigned arr = atomicAdd(&g_cnt, 1u);
        if (arr == (unsigned)(NBLK - 1)) {
            atomicExch(&g_cnt, 0u);
            __threadfence();
            atomicExch(&g_gen, gen + 1u);
        } else {
            while (*((volatile unsigned*)&g_gen) == gen) { }
            __threadfence();
        }
    }
    __syncthreads();
    gen += 1u;
}

// ---------------- embedding gather + best reset ----------------
__global__ void k_embed(const int* __restrict__ src, const int* __restrict__ dst,
                        const float* __restrict__ wte,
                        float* __restrict__ src_e, float* __restrict__ dst_e) {
    size_t i = (size_t)blockIdx.x * blockDim.x + threadIdx.x;
    if (i < 1024) g_best[i] = 0ull;
    const size_t n1 = (size_t)BATCH * SLEN * DIM;
    if (i < n1) {
        int row = (int)(i / DIM), k = (int)(i % DIM);
        src_e[i] = wte[(size_t)src[row] * DIM + k];
    } else {
        size_t ii = i - n1;
        if (ii < (size_t)BATCH * TLEN * DIM) {
            int row = (int)(ii / DIM), k = (int)(ii % DIM);
            dst_e[ii] = wte[(size_t)dst[row] * DIM + k];
        }
    }
}

// ---------------- NT sgemm: C[m,n] = sum_k A[m,k]*B[n,k] + bias[n] (+resid) ----------
// 128x128x16 tile, 8x8 per thread, 256 threads. M must be a multiple of 128.
// AM=true: fused row-argmax via atomicMax into g_best (C not written).
template <bool AM>
__global__ __launch_bounds__(256) void k_sgemm_nt(
    const float* __restrict__ A, const float* __restrict__ B,
    const float* __restrict__ bias, float* __restrict__ C,
    const float* __restrict__ resid, int M, int N, int K)
{
    __shared__ float As[16][132];
    __shared__ float Bs[16][132];
    int tid = threadIdx.x;
    int tx = tid & 15, ty = tid >> 4;
    int m0 = blockIdx.y * 128, n0 = blockIdx.x * 128;
    int lrow = tid >> 2;
    int lcol = (tid & 3) << 2;

    float acc[8][8];
#pragma unroll
    for (int i = 0; i < 8; ++i)
#pragma unroll
        for (int j = 0; j < 8; ++j) acc[i][j] = 0.f;

    for (int kt = 0; kt < K; kt += 16) {
#pragma unroll
        for (int i = 0; i < 2; ++i) {
            int r = lrow + i * 64;
            float4 v = *(const float4*)(A + (size_t)(m0 + r) * K + kt + lcol);
            As[lcol + 0][r] = v.x; As[lcol + 1][r] = v.y;
            As[lcol + 2][r] = v.z; As[lcol + 3][r] = v.w;
            int n = n0 + r;
            float4 u = make_float4(0.f, 0.f, 0.f, 0.f);
            if (n < N) u = *(const float4*)(B + (size_t)n * K + kt + lcol);
            Bs[lcol + 0][r] = u.x; Bs[lcol + 1][r] = u.y;
            Bs[lcol + 2][r] = u.z; Bs[lcol + 3][r] = u.w;
        }
        __syncthreads();
#pragma unroll
        for (int kk = 0; kk < 16; ++kk) {
            float a[8], b[8];
            *(float4*)&a[0] = *(const float4*)&As[kk][ty * 4];
            *(float4*)&a[4] = *(const float4*)&As[kk][64 + ty * 4];
            *(float4*)&b[0] = *(const float4*)&Bs[kk][tx * 4];
            *(float4*)&b[4] = *(const float4*)&Bs[kk][64 + tx * 4];
#pragma unroll
            for (int i = 0; i < 8; ++i)
#pragma unroll
                for (int j = 0; j < 8; ++j)
                    acc[i][j] = fmaf(a[i], b[j], acc[i][j]);
        }
        __syncthreads();
    }

    int mi[8], nj[8];
#pragma unroll
    for (int i = 0; i < 4; ++i) {
        mi[i] = ty * 4 + i; mi[i + 4] = 64 + ty * 4 + i;
        nj[i] = tx * 4 + i; nj[i + 4] = 64 + tx * 4 + i;
    }

    if (!AM) {
#pragma unroll
        for (int i = 0; i < 8; ++i) {
            size_t m = (size_t)(m0 + mi[i]);
#pragma unroll
            for (int j = 0; j < 8; ++j) {
                int n = n0 + nj[j];
                if (n < N) {
                    float v = acc[i][j] + bias[n];
                    if (resid) v += resid[m * (size_t)N + n];
                    C[m * (size_t)N + n] = v;
                }
            }
        }
    } else {
        __shared__ unsigned long long red[128][17];
#pragma unroll
        for (int i = 0; i < 8; ++i) {
            unsigned long long lb = 0ull;
#pragma unroll
            for (int j = 0; j < 8; ++j) {
                int n = n0 + nj[j];
                if (n < N) {
                    float f = acc[i][j] + bias[n];
                    unsigned u = __float_as_uint(f);
                    unsigned key = (u & 0x80000000u) ? ~u : (u | 0x80000000u);
                    unsigned long long pk =
                        ((unsigned long long)key << 32) |
                        (unsigned long long)(0xFFFFFFFFu - (unsigned)n);
                    if (pk > lb) lb = pk;   // equal value -> smaller n wins
                }
            }
            red[mi[i]][tx] = lb;
        }
        __syncthreads();
        if (tid < 128) {
            unsigned long long bb = 0ull;
#pragma unroll
            for (int x = 0; x < 16; ++x) {
                unsigned long long v = red[tid][x];
                if (v > bb) bb = v;
            }
            atomicMax(&g_best[m0 + tid], bb);
        }
    }
}

// ---------------- persistent GRU scan (input gates precomputed in gi) ----------------
// 96 blocks x 256 threads: warp w of block bx owns output unit j = bx*8+w.
// One grid barrier per step; hidden ping-pongs in g_h.
__global__ __launch_bounds__(256) void k_gru_scan_p(
    const float* __restrict__ gi,     // [(b*T+t), 2304]
    const float* __restrict__ w_hh,   // [2304,768]
    const float* __restrict__ b_hh,
    const int* __restrict__ lens,
    const float* __restrict__ h0,     // null -> zeros
    float* __restrict__ out_seq,      // null or [(b*T+t),768] zero-padded
    float* __restrict__ h_final,      // null or [8,768]
    int T)
{
    int w = threadIdx.x >> 5, lane = threadIdx.x & 31;
    int j = blockIdx.x * 8 + w;
    unsigned gen = *((volatile unsigned*)&g_gen);

    if (lane < 8)
        g_h[0][lane * DIM + j] = h0 ? h0[lane * DIM + j] : 0.f;
    gbar(gen);

    const float* wr = w_hh + (size_t)j * DIM;
    const float* wz = w_hh + (size_t)(DIM + j) * DIM;
    const float* wn = w_hh + (size_t)(2 * DIM + j) * DIM;
    float bhr = b_hh[j], bhz = b_hh[DIM + j], bhn = b_hh[2 * DIM + j];
    int mylen = lens[lane & 7];

    for (int t = 0; t < T; ++t) {
        const float* hin = g_h[t & 1];
        float ar[8], az[8], an[8];
#pragma unroll
        for (int b = 0; b < 8; ++b) { ar[b] = 0.f; az[b] = 0.f; an[b] = 0.f; }
        for (int k = lane; k < DIM; k += 32) {
            float w0 = wr[k], w1 = wz[k], w2 = wn[k];
#pragma unroll
            for (int b = 0; b < 8; ++b) {
                float hv = hin[b * DIM + k];
                ar[b] = fmaf(w0, hv, ar[b]);
                az[b] = fmaf(w1, hv, az[b]);
                an[b] = fmaf(w2, hv, an[b]);
            }
        }
#pragma unroll
        for (int b = 0; b < 8; ++b) {
#pragma unroll
            for (int o = 16; o; o >>= 1) {
                ar[b] += __shfl_xor_sync(0xFFFFFFFFu, ar[b], o);
                az[b] += __shfl_xor_sync(0xFFFFFFFFu, az[b], o);
                an[b] += __shfl_xor_sync(0xFFFFFFFFu, an[b], o);
            }
        }
        if (lane < 8) {
            int b = lane;
            const float* gib = gi + (size_t)(b * T + t) * D3;
            float hold = hin[b * DIM + j];
            float r = sigm(gib[j] + ar[b] + bhr);
            float z = sigm(gib[DIM + j] + az[b] + bhz);
            float n = tanhf(gib[2 * DIM + j] + r * (an[b] + bhn));
            float hn = (1.f - z) * n + z * hold;
            bool valid = (t < mylen);
            g_h[(t + 1) & 1][b * DIM + j] = valid ? hn : hold;
            if (out_seq) out_seq[(size_t)(b * T + t) * DIM + j] = valid ? hn : 0.f;
        }
        gbar(gen);
    }
    if (h_final && lane < 8)
        h_final[lane * DIM + j] = g_h[T & 1][lane * DIM + j];
}

// ---------------- persistent scheduled-sampling decode ----------------
// Step 0: h0 = cell(dst_e[:,0], g_henc). Then 127x {argmax(h+gumbel) -> oracle,
// cell(wte[oracle], h)}. All in one kernel; oracle computed per block (warp b
// handles batch b, redundant across blocks, deterministic).
__global__ __launch_bounds__(256) void k_decode_p(
    const float* __restrict__ dst_e, const float* __restrict__ wte,
    const float* __restrict__ w_ih, const float* __restrict__ w_hh,
    const float* __restrict__ b_ih, const float* __restrict__ b_hh,
    const float* __restrict__ gumbel, float* __restrict__ fout)
{
    __shared__ int s_orac[8];
    int w = threadIdx.x >> 5, lane = threadIdx.x & 31;
    int j = blockIdx.x * 8 + w;
    unsigned gen = *((volatile unsigned*)&g_gen);

    const float* wir = w_ih + (size_t)j * DIM;
    const float* wiz = w_ih + (size_t)(DIM + j) * DIM;
    const float* win = w_ih + (size_t)(2 * DIM + j) * DIM;
    const float* whr = w_hh + (size_t)j * DIM;
    const float* whz = w_hh + (size_t)(DIM + j) * DIM;
    const float* whn = w_hh + (size_t)(2 * DIM + j) * DIM;
    float bir = b_ih[j], biz = b_ih[DIM + j], bin_ = b_ih[2 * DIM + j];
    float bhr = b_hh[j], bhz = b_hh[DIM + j], bhn = b_hh[2 * DIM + j];

    for (int t = 0; t <= TLEN - 1; ++t) {
        const float* hin = (t == 0) ? g_henc : g_h[(t + 1) & 1];

        const float* xp[8];
        if (t == 0) {
#pragma unroll
            for (int b = 0; b < 8; ++b)
                xp[b] = dst_e + (size_t)b * TLEN * DIM;    // dst_e[:,0,:]
        } else {
            // oracle = argmax over D of h + gumbel[t-1]; warp w owns batch w
            {
                const float* gp = gumbel + ((size_t)(t - 1) * BATCH + w) * DIM;
                const float* hp = hin + w * DIM;
                float bv = -INFINITY; int bi = 0x7FFFFFFF;
                for (int i = lane; i < DIM; i += 32) {
                    float v = hp[i] + gp[i];
                    if (v > bv || (v == bv && i < bi)) { bv = v; bi = i; }
                }
#pragma unroll
                for (int o = 16; o; o >>= 1) {
                    float ov = __shfl_xor_sync(0xFFFFFFFFu, bv, o);
                    int   oi = __shfl_xor_sync(0xFFFFFFFFu, bi, o);
                    if (ov > bv || (ov == bv && oi < bi)) { bv = ov; bi = oi; }
                }
                if (lane == 0) s_orac[w] = bi;
            }
            __syncthreads();
#pragma unroll
            for (int b = 0; b < 8; ++b)
                xp[b] = wte + (size_t)s_orac[b] * DIM;
        }

        float ir[8], iz[8], inn[8], hr[8], hz[8], hn[8];
#pragma unroll
        for (int b = 0; b < 8; ++b) { ir[b]=iz[b]=inn[b]=hr[b]=hz[b]=hn[b]=0.f; }
        for (int k = lane; k < DIM; k += 32) {
            float a0 = wir[k], a1 = wiz[k], a2 = win[k];
            float c0 = whr[k], c1 = whz[k], c2 = whn[k];
#pragma unroll
            for (int b = 0; b < 8; ++b) {
                float xv = xp[b][k];
                float hv = hin[b * DIM + k];
                ir[b]  = fmaf(a0, xv, ir[b]);
                iz[b]  = fmaf(a1, xv, iz[b]);
                inn[b] = fmaf(a2, xv, inn[b]);
                hr[b]  = fmaf(c0, hv, hr[b]);
                hz[b]  = fmaf(c1, hv, hz[b]);
                hn[b]  = fmaf(c2, hv, hn[b]);
            }
        }
#pragma unroll
        for (int b = 0; b < 8; ++b) {
#pragma unroll
            for (int o = 16; o; o >>= 1) {
                ir[b]  += __shfl_xor_sync(0xFFFFFFFFu, ir[b], o);
                iz[b]  += __shfl_xor_sync(0xFFFFFFFFu, iz[b], o);
                inn[b] += __shfl_xor_sync(0xFFFFFFFFu, inn[b], o);
                hr[b]  += __shfl_xor_sync(0xFFFFFFFFu, hr[b], o);
                hz[b]  += __shfl_xor_sync(0xFFFFFFFFu, hz[b], o);
                hn[b]  += __shfl_xor_sync(0xFFFFFFFFu, hn[b], o);
            }
        }
        if (lane < 8) {
            int b = lane;
            float hold = hin[b * DIM + j];
            float r = sigm(ir[b] + bir + hr[b] + bhr);
            float z = sigm(iz[b] + biz + hz[b] + bhz);
            float n = tanhf(inn[b] + bin_ + r * (hn[b] + bhn));
            float hv = (1.f - z) * n + z * hold;
            g_h[t & 1][b * DIM + j] = hv;
            fout[(size_t)(b * TLEN + t) * DIM + j] = hv;
        }
        gbar(gen);
    }
}

// ---------------- misc small kernels ----------------
__global__ void k_gather_cand(const float* __restrict__ wte, float* __restrict__ cand) {
    size_t i = (size_t)blockIdx.x * blockDim.x + threadIdx.x;
    if (i < (size_t)1024 * DIM) {
        int m = (int)(i / DIM), k = (int)(i % DIM);
        unsigned id = 0xFFFFFFFFu - (unsigned)(g_best[m] & 0xFFFFFFFFull);
        cand[i] = wte[(size_t)id * DIM + k];
    }
}

// ---------------- attention: one block per (b,h); thread per query s ----------------
__global__ __launch_bounds__(256) void k_attn(
    const float* __restrict__ q, const float* __restrict__ kk,
    const float* __restrict__ vv, const int* __restrict__ dlen,
    float* __restrict__ ao)
{
    __shared__ float Ks[64][65];
    __shared__ float Vs[64][65];
    int b = blockIdx.x / NHEAD, h = blockIdx.x % NHEAD;
    int s = threadIdx.x;
    int len = dlen[b];

    float qv[HDIM];
    const float* qp = q + ((size_t)(b * SLEN + s)) * DIM + h * HDIM;
#pragma unroll
    for (int d = 0; d < HDIM; ++d) qv[d] = qp[d] * 0.125f;   // 1/sqrt(64)

    float m = -INFINITY, l = 0.f;
    float o[HDIM];
#pragma unroll
    for (int d = 0; d < HDIM; ++d) o[d] = 0.f;

    for (int c = 0; c < 2; ++c) {
        for (int i = threadIdx.x; i < 1024; i += 256) {
            int row = i >> 4, c4 = (i & 15) << 2;
            size_t base = ((size_t)(b * TLEN + c * 64 + row)) * DIM + h * HDIM + c4;
            float4 kvv = *(const float4*)(kk + base);
            float4 vvv = *(const float4*)(vv + base);
            Ks[row][c4 + 0] = kvv.x; Ks[row][c4 + 1] = kvv.y;
            Ks[row][c4 + 2] = kvv.z; Ks[row][c4 + 3] = kvv.w;
            Vs[row][c4 + 0] = vvv.x; Vs[row][c4 + 1] = vvv.y;
            Vs[row][c4 + 2] = vvv.z; Vs[row][c4 + 3] = vvv.w;
        }
        __syncthreads();
        for (int tc = 0; tc < 64; ++tc) {
            int t = c * 64 + tc;
            float sc = 0.f;
#pragma unroll
            for (int d = 0; d < HDIM; ++d) sc = fmaf(qv[d], Ks[tc][d], sc);
            if (t >= len) sc = -1e9f;
            float mn = fmaxf(m, sc);
            float scale = expf(m - mn);       // exp(-inf)=0 on first iteration
            float p = expf(sc - mn);
            l = l * scale + p;
#pragma unroll
            for (int d = 0; d < HDIM; ++d)
                o[d] = o[d] * scale + p * Vs[tc][d];
            m = mn;
        }
        __syncthreads();
    }
    float inv = 1.f / l;
    float* op = ao + ((size_t)(b * SLEN + s)) * DIM + h * HDIM;
#pragma unroll
    for (int d = 0; d < HDIM; ++d) op[d] = o[d] * inv;
}

// ---------------- latent loss (deterministic, fixed partition) ----------------
__global__ void k_loss_part(const float* __restrict__ a, const float* __restrict__ b) {
    __shared__ double red[256];
    int blk = blockIdx.x, tid = threadIdx.x;
    size_t base = (size_t)blk * 3072;
    double s = 0.0;
    for (int i = tid; i < 3072; i += 256) {
        double d = (double)a[base + i] - (double)b[base + i];
        s += d * d;
    }
    red[tid] = s;
    __syncthreads();
    for (int o = 128; o; o >>= 1) {
        if (tid < o) red[tid] += red[tid + o];
        __syncthreads();
    }
    if (tid == 0) g_part[blk] = red[0];
}
__global__ void k_loss_final(float* __restrict__ out) {
    if (threadIdx.x == 0) {
        double s = 0.0;
        for (int i = 0; i < 512; ++i) s += g_part[i];
        out[(size_t)1024 * VOC] = (float)s;
    }
}

// ---------------- host driver ----------------
extern "C" void kernel_launch(void* const* d_in, const int* in_sizes, int n_in,
                              void* d_out, int out_size) {
    const int*   src      = (const int*)d_in[0];
    const int*   src_len  = (const int*)d_in[1];
    const int*   dst      = (const int*)d_in[2];
    const int*   dst_len  = (const int*)d_in[3];
    const float* wte      = (const float*)d_in[4];
    const float* e_wih    = (const float*)d_in[5];
    const float* e_whh    = (const float*)d_in[6];
    const float* e_bih    = (const float*)d_in[7];
    const float* e_bhh    = (const float*)d_in[8];
    const float* d_wih    = (const float*)d_in[9];
    const float* d_whh    = (const float*)d_in[10];
    const float* d_bih    = (const float*)d_in[11];
    const float* d_bhh    = (const float*)d_in[12];
    const float* out_w    = (const float*)d_in[13];
    const float* out_b    = (const float*)d_in[14];
    const float* ll_w     = (const float*)d_in[15];
    const float* ll_b     = (const float*)d_in[16];
    const float* a_inw    = (const float*)d_in[17];
    const float* a_inb    = (const float*)d_in[18];
    const float* a_ow     = (const float*)d_in[19];
    const float* a_ob     = (const float*)d_in[20];
    const float* gumbel   = (const float*)d_in[21];
    float* y = (float*)d_out;

    float* gb = nullptr;    cudaGetSymbolAddress((void**)&gb, g_buf);
    float* hbuf0 = nullptr; cudaGetSymbolAddress((void**)&hbuf0, g_h);
    float* henc = nullptr;  cudaGetSymbolAddress((void**)&henc, g_henc);

    float* src_e  = gb + OFF_SRC_E;
    float* dst_e  = gb + OFF_DST_E;
    float* gi     = gb + OFF_GI;
    float* finalo = gb + OFF_FINAL;
    float* cand   = gb + OFF_CAND;
    float* qb     = gb + OFF_Q;
    float* kb     = gb + OFF_KP;
    float* vb     = gb + OFF_VP;
    float* aob    = gb + OFF_AO;
    float* coutb  = gb + OFF_COUT;
    float* caftb  = gb + OFF_CAFT;
    float* dstout = gb + OFF_DSTOUT;

    // 1) embeddings + best reset
    k_embed<<<9216, 256>>>(src, dst, wte, src_e, dst_e);

    // 2) encoder scan 1 (persistent); h_enc -> g_henc
    k_sgemm_nt<false><<<dim3(18, 16), 256>>>(src_e, e_wih, e_bih, gi, nullptr, 2048, D3, DIM);
    k_gru_scan_p<<<NBLK, 256>>>(gi, e_whh, e_bhh, src_len, nullptr, nullptr, henc, SLEN);

    // 3) scheduled-sampling decode (persistent) -> finalo
    k_decode_p<<<NBLK, 256>>>(dst_e, wte, d_wih, d_whh, d_bih, d_bhh, gumbel, finalo);

    // 4) cand logits + fused argmax; gather cand embeddings
    k_sgemm_nt<true><<<dim3(393, 8), 256>>>(finalo, out_w, out_b, nullptr, nullptr, 1024, VOC, DIM);
    k_gather_cand<<<3072, 256>>>(wte, cand);

    // 5) attention
    k_sgemm_nt<false><<<dim3(6, 16), 256>>>(src_e, a_inw,              a_inb,        qb, nullptr, 2048, DIM, DIM);
    k_sgemm_nt<false><<<dim3(6, 8),  256>>>(cand,  a_inw + 768 * 768,  a_inb + 768,  kb, nullptr, 1024, DIM, DIM);
    k_sgemm_nt<false><<<dim3(6, 8),  256>>>(cand,  a_inw + 1536 * 768, a_inb + 1536, vb, nullptr, 1024, DIM, DIM);
    k_attn<<<96, 256>>>(qb, kb, vb, dst_len, aob);
    k_sgemm_nt<false><<<dim3(6, 16), 256>>>(aob, a_ow, a_ob, coutb, src_e, 2048, DIM, DIM);

    // 6) c_aft + latent loss (c_multi == c_output since PARAM1=0, PARAM2=1)
    k_sgemm_nt<false><<<dim3(6, 16), 256>>>(src_e, ll_w, ll_b, caftb, nullptr, 2048, DIM, DIM);
    k_loss_part<<<512, 256>>>(caftb, coutb);
    k_loss_final<<<1, 32>>>(y);

    // 7) encoder scan 2 on c_output (persistent); final hidden left in g_h[0]
    k_sgemm_nt<false><<<dim3(18, 16), 256>>>(coutb, e_wih, e_bih, gi, nullptr, 2048, D3, DIM);
    k_gru_scan_p<<<NBLK, 256>>>(gi, e_whh, e_bhh, src_len, nullptr, nullptr, nullptr, SLEN);

    // 8) decoder scan (persistent), h0 = g_h[0] (identity re-init), out zero-padded
    k_sgemm_nt<false><<<dim3(18, 8), 256>>>(dst_e, d_wih, d_bih, gi, nullptr, 1024, D3, DIM);
    k_gru_scan_p<<<NBLK, 256>>>(gi, d_whh, d_bhh, dst_len, hbuf0, dstout, nullptr, TLEN);

    // 9) y = dst_out @ out_w^T + out_b
    k_sgemm_nt<false><<<dim3(393, 8), 256>>>(dstout, out_w, out_b, y, nullptr, 1024, VOC, DIM);
}

// round 10
// speedup vs baseline: 1.0290x; 1.0290x over previous
#include <cuda_runtime.h>
#include <math.h>

#define DIM   768
#define D3    2304
#define BATCH 8
#define SLEN  256
#define TLEN  128
#define VOC   50257
#define NHEAD 12
#define HDIM  64
#define NBLK  96

// ---------------- scratch (device globals; no allocation) ----------------
__device__ float g_buf[17301504];          // ~66 MB
__device__ float g_h[2][BATCH * DIM];      // GRU hidden ping-pong
__device__ float g_henc[BATCH * DIM];
__device__ unsigned long long g_best[1024];
__device__ double g_part[512];
__device__ unsigned g_cnt = 0;
__device__ unsigned g_gen = 0;

// g_buf offsets (floats)
#define OFF_SRC_E  0u
#define OFF_DST_E  1572864u
#define OFF_GI     2359296u
#define OFF_FINAL  7077888u
#define OFF_CAND   7864320u
#define OFF_Q      8650752u
#define OFF_KP     10223616u
#define OFF_VP     11010048u
#define OFF_AO     11796480u
#define OFF_COUT   13369344u
#define OFF_CAFT   14942208u
#define OFF_DSTOUT 16515072u

__device__ __forceinline__ float sigm(float x) { return 1.0f / (1.0f + expf(-x)); }

// ---- packed f32x2 helpers (Blackwell sm_103a) ----
__device__ __forceinline__ unsigned long long packf2(float lo, float hi) {
    unsigned long long r;
    asm("mov.b64 %0, {%1, %2};" : "=l"(r) : "f"(lo), "f"(hi));
    return r;
}
__device__ __forceinline__ void unpackf2(unsigned long long v, float& lo, float& hi) {
    asm("mov.b64 {%0, %1}, %2;" : "=f"(lo), "=f"(hi) : "l"(v));
}
__device__ __forceinline__ void fma2(unsigned long long& d,
                                     unsigned long long a, unsigned long long b) {
    asm("fma.rn.f32x2 %0, %1, %2, %0;" : "+l"(d) : "l"(a), "l"(b));
}

// Grid barrier for NBLK co-resident blocks (generation-based, monotone g_gen).
__device__ __forceinline__ void gbar(unsigned& gen) {
    __syncthreads();
    if (threadIdx.x == 0) {
        __threadfence();
        unsigned arr = atomicAdd(&g_cnt, 1u);
        if (arr == (unsigned)(NBLK - 1)) {
            atomicExch(&g_cnt, 0u);
            __threadfence();
            atomicExch(&g_gen, gen + 1u);
        } else {
            while (*((volatile unsigned*)&g_gen) == gen) { }
            __threadfence();
        }
    }
    __syncthreads();
    gen += 1u;
}

// ---------------- embedding gather + best reset ----------------
__global__ void k_embed(const int* __restrict__ src, const int* __restrict__ dst,
                        const float* __restrict__ wte,
                        float* __restrict__ src_e, float* __restrict__ dst_e) {
    size_t i = (size_t)blockIdx.x * blockDim.x + threadIdx.x;
    if (i < 1024) g_best[i] = 0ull;
    const size_t n1 = (size_t)BATCH * SLEN * DIM;
    if (i < n1) {
        int row = (int)(i / DIM), k = (int)(i % DIM);
        src_e[i] = wte[(size_t)src[row] * DIM + k];
    } else {
        size_t ii = i - n1;
        if (ii < (size_t)BATCH * TLEN * DIM) {
            int row = (int)(ii / DIM), k = (int)(ii % DIM);
            dst_e[ii] = wte[(size_t)dst[row] * DIM + k];
        }
    }
}

// ---------------- NT sgemm with packed f32x2 FMA ----------------
// C[m,n] = sum_k A[m,k]*B[n,k] + bias[n] (+resid). 128x128x16 tile,
// 8x8 per thread (as 4 m-pairs x 8 n), 256 threads. M % 128 == 0.
// AM=true: fused row-argmax via atomicMax into g_best (C not written).
template <bool AM>
__global__ __launch_bounds__(256) void k_sgemm_nt(
    const float* __restrict__ A, const float* __restrict__ B,
    const float* __restrict__ bias, float* __restrict__ C,
    const float* __restrict__ resid, int M, int N, int K)
{
    __shared__ float As[16][132];
    __shared__ float Bs[16][132];
    int tid = threadIdx.x;
    int tx = tid & 15, ty = tid >> 4;
    int m0 = blockIdx.y * 128, n0 = blockIdx.x * 128;
    int lrow = tid >> 2;
    int lcol = (tid & 3) << 2;
    int r0 = lrow, r1 = lrow + 64;

    unsigned long long acc2[4][8];
#pragma unroll
    for (int p = 0; p < 4; ++p)
#pragma unroll
        for (int j = 0; j < 8; ++j) acc2[p][j] = 0ull;

    const float* Ap0 = A + (size_t)(m0 + r0) * K + lcol;
    const float* Ap1 = A + (size_t)(m0 + r1) * K + lcol;
    bool bv0 = (n0 + r0) < N, bv1 = (n0 + r1) < N;
    const float* Bp0 = B + (size_t)(n0 + r0) * K + lcol;
    const float* Bp1 = B + (size_t)(n0 + r1) * K + lcol;

    const float4 z4 = make_float4(0.f, 0.f, 0.f, 0.f);
    float4 pa0 = *(const float4*)(Ap0);
    float4 pa1 = *(const float4*)(Ap1);
    float4 pb0 = bv0 ? *(const float4*)(Bp0) : z4;
    float4 pb1 = bv1 ? *(const float4*)(Bp1) : z4;

    for (int kt = 0; kt < K; kt += 16) {
        As[lcol + 0][r0] = pa0.x; As[lcol + 1][r0] = pa0.y;
        As[lcol + 2][r0] = pa0.z; As[lcol + 3][r0] = pa0.w;
        As[lcol + 0][r1] = pa1.x; As[lcol + 1][r1] = pa1.y;
        As[lcol + 2][r1] = pa1.z; As[lcol + 3][r1] = pa1.w;
        Bs[lcol + 0][r0] = pb0.x; Bs[lcol + 1][r0] = pb0.y;
        Bs[lcol + 2][r0] = pb0.z; Bs[lcol + 3][r0] = pb0.w;
        Bs[lcol + 0][r1] = pb1.x; Bs[lcol + 1][r1] = pb1.y;
        Bs[lcol + 2][r1] = pb1.z; Bs[lcol + 3][r1] = pb1.w;
        __syncthreads();

        if (kt + 16 < K) {   // prefetch next k-tile while this one computes
            pa0 = *(const float4*)(Ap0 + kt + 16);
            pa1 = *(const float4*)(Ap1 + kt + 16);
            pb0 = bv0 ? *(const float4*)(Bp0 + kt + 16) : z4;
            pb1 = bv1 ? *(const float4*)(Bp1 + kt + 16) : z4;
        }

#pragma unroll
        for (int kk = 0; kk < 16; ++kk) {
            float4 af0 = *(const float4*)&As[kk][ty * 4];
            float4 af1 = *(const float4*)&As[kk][64 + ty * 4];
            unsigned long long ap[4];
            ap[0] = packf2(af0.x, af0.y);
            ap[1] = packf2(af0.z, af0.w);
            ap[2] = packf2(af1.x, af1.y);
            ap[3] = packf2(af1.z, af1.w);
            float4 bf0 = *(const float4*)&Bs[kk][tx * 4];
            float4 bf1 = *(const float4*)&Bs[kk][64 + tx * 4];
            unsigned long long bd[8];
            bd[0] = packf2(bf0.x, bf0.x); bd[1] = packf2(bf0.y, bf0.y);
            bd[2] = packf2(bf0.z, bf0.z); bd[3] = packf2(bf0.w, bf0.w);
            bd[4] = packf2(bf1.x, bf1.x); bd[5] = packf2(bf1.y, bf1.y);
            bd[6] = packf2(bf1.z, bf1.z); bd[7] = packf2(bf1.w, bf1.w);
#pragma unroll
            for (int p = 0; p < 4; ++p)
#pragma unroll
                for (int j = 0; j < 8; ++j)
                    fma2(acc2[p][j], ap[p], bd[j]);
        }
        __syncthreads();
    }

    if (!AM) {
#pragma unroll
        for (int p = 0; p < 4; ++p) {
            int i0 = (p < 2) ? (ty * 4 + 2 * p) : (64 + ty * 4 + 2 * p - 4);
            size_t mA = (size_t)(m0 + i0);
            size_t mB = mA + 1;
#pragma unroll
            for (int j = 0; j < 8; ++j) {
                int n = n0 + ((j < 4) ? tx * 4 + j : 64 + tx * 4 + j - 4);
                if (n < N) {
                    float lo, hi; unpackf2(acc2[p][j], lo, hi);
                    float bnv = bias[n];
                    float va = lo + bnv, vb = hi + bnv;
                    if (resid) {
                        va += resid[mA * (size_t)N + n];
                        vb += resid[mB * (size_t)N + n];
                    }
                    C[mA * (size_t)N + n] = va;
                    C[mB * (size_t)N + n] = vb;
                }
            }
        }
    } else {
        __shared__ unsigned long long red[128][17];
#pragma unroll
        for (int p = 0; p < 4; ++p) {
            int i0 = (p < 2) ? (ty * 4 + 2 * p) : (64 + ty * 4 + 2 * p - 4);
            unsigned long long lb0 = 0ull, lb1 = 0ull;
#pragma unroll
            for (int j = 0; j < 8; ++j) {
                int n = n0 + ((j < 4) ? tx * 4 + j : 64 + tx * 4 + j - 4);
                if (n < N) {
                    float lo, hi; unpackf2(acc2[p][j], lo, hi);
                    float bnv = bias[n];
                    {
                        unsigned u = __float_as_uint(lo + bnv);
                        unsigned key = (u & 0x80000000u) ? ~u : (u | 0x80000000u);
                        unsigned long long pk = ((unsigned long long)key << 32) |
                            (unsigned long long)(0xFFFFFFFFu - (unsigned)n);
                        if (pk > lb0) lb0 = pk;
                    }
                    {
                        unsigned u = __float_as_uint(hi + bnv);
                        unsigned key = (u & 0x80000000u) ? ~u : (u | 0x80000000u);
                        unsigned long long pk = ((unsigned long long)key << 32) |
                            (unsigned long long)(0xFFFFFFFFu - (unsigned)n);
                        if (pk > lb1) lb1 = pk;
                    }
                }
            }
            red[i0][tx] = lb0;
            red[i0 + 1][tx] = lb1;
        }
        __syncthreads();
        if (tid < 128) {
            unsigned long long bb = 0ull;
#pragma unroll
            for (int x = 0; x < 16; ++x) {
                unsigned long long v = red[tid][x];
                if (v > bb) bb = v;
            }
            atomicMax(&g_best[m0 + tid], bb);
        }
    }
}

// ---------------- persistent GRU scan (input gates precomputed in gi) ----------------
__global__ __launch_bounds__(256) void k_gru_scan_p(
    const float* __restrict__ gi, const float* __restrict__ w_hh,
    const float* __restrict__ b_hh, const int* __restrict__ lens,
    const float* __restrict__ h0, float* __restrict__ out_seq,
    float* __restrict__ h_final, int T)
{
    int w = threadIdx.x >> 5, lane = threadIdx.x & 31;
    int j = blockIdx.x * 8 + w;
    unsigned gen = *((volatile unsigned*)&g_gen);

    if (lane < 8)
        g_h[0][lane * DIM + j] = h0 ? h0[lane * DIM + j] : 0.f;
    gbar(gen);

    const float* wr = w_hh + (size_t)j * DIM;
    const float* wz = w_hh + (size_t)(DIM + j) * DIM;
    const float* wn = w_hh + (size_t)(2 * DIM + j) * DIM;
    float bhr = b_hh[j], bhz = b_hh[DIM + j], bhn = b_hh[2 * DIM + j];
    int mylen = lens[lane & 7];

    for (int t = 0; t < T; ++t) {
        const float* hin = g_h[t & 1];
        float ar[8], az[8], an[8];
#pragma unroll
        for (int b = 0; b < 8; ++b) { ar[b] = 0.f; az[b] = 0.f; an[b] = 0.f; }
        for (int k = lane; k < DIM; k += 32) {
            float w0 = wr[k], w1 = wz[k], w2 = wn[k];
#pragma unroll
            for (int b = 0; b < 8; ++b) {
                float hv = hin[b * DIM + k];
                ar[b] = fmaf(w0, hv, ar[b]);
                az[b] = fmaf(w1, hv, az[b]);
                an[b] = fmaf(w2, hv, an[b]);
            }
        }
#pragma unroll
        for (int b = 0; b < 8; ++b) {
#pragma unroll
            for (int o = 16; o; o >>= 1) {
                ar[b] += __shfl_xor_sync(0xFFFFFFFFu, ar[b], o);
                az[b] += __shfl_xor_sync(0xFFFFFFFFu, az[b], o);
                an[b] += __shfl_xor_sync(0xFFFFFFFFu, an[b], o);
            }
        }
        if (lane < 8) {
            int b = lane;
            const float* gib = gi + (size_t)(b * T + t) * D3;
            float hold = hin[b * DIM + j];
            float r = sigm(gib[j] + ar[b] + bhr);
            float z = sigm(gib[DIM + j] + az[b] + bhz);
            float n = tanhf(gib[2 * DIM + j] + r * (an[b] + bhn));
            float hn = (1.f - z) * n + z * hold;
            bool valid = (t < mylen);
            g_h[(t + 1) & 1][b * DIM + j] = valid ? hn : hold;
            if (out_seq) out_seq[(size_t)(b * T + t) * DIM + j] = valid ? hn : 0.f;
        }
        gbar(gen);
    }
    if (h_final && lane < 8)
        h_final[lane * DIM + j] = g_h[T & 1][lane * DIM + j];
}

// ---------------- persistent scheduled-sampling decode ----------------
__global__ __launch_bounds__(256) void k_decode_p(
    const float* __restrict__ dst_e, const float* __restrict__ wte,
    const float* __restrict__ w_ih, const float* __restrict__ w_hh,
    const float* __restrict__ b_ih, const float* __restrict__ b_hh,
    const float* __restrict__ gumbel, float* __restrict__ fout)
{
    __shared__ int s_orac[8];
    int w = threadIdx.x >> 5, lane = threadIdx.x & 31;
    int j = blockIdx.x * 8 + w;
    unsigned gen = *((volatile unsigned*)&g_gen);

    const float* wir = w_ih + (size_t)j * DIM;
    const float* wiz = w_ih + (size_t)(DIM + j) * DIM;
    const float* win = w_ih + (size_t)(2 * DIM + j) * DIM;
    const float* whr = w_hh + (size_t)j * DIM;
    const float* whz = w_hh + (size_t)(DIM + j) * DIM;
    const float* whn = w_hh + (size_t)(2 * DIM + j) * DIM;
    float bir = b_ih[j], biz = b_ih[DIM + j], bin_ = b_ih[2 * DIM + j];
    float bhr = b_hh[j], bhz = b_hh[DIM + j], bhn = b_hh[2 * DIM + j];

    for (int t = 0; t <= TLEN - 1; ++t) {
        const float* hin = (t == 0) ? g_henc : g_h[(t + 1) & 1];

        const float* xp[8];
        if (t == 0) {
#pragma unroll
            for (int b = 0; b < 8; ++b)
                xp[b] = dst_e + (size_t)b * TLEN * DIM;    // dst_e[:,0,:]
        } else {
            {
                const float* gp = gumbel + ((size_t)(t - 1) * BATCH + w) * DIM;
                const float* hp = hin + w * DIM;
                float bv = -INFINITY; int bi = 0x7FFFFFFF;
                for (int i = lane; i < DIM; i += 32) {
                    float v = hp[i] + gp[i];
                    if (v > bv || (v == bv && i < bi)) { bv = v; bi = i; }
                }
#pragma unroll
                for (int o = 16; o; o >>= 1) {
                    float ov = __shfl_xor_sync(0xFFFFFFFFu, bv, o);
                    int   oi = __shfl_xor_sync(0xFFFFFFFFu, bi, o);
                    if (ov > bv || (ov == bv && oi < bi)) { bv = ov; bi = oi; }
                }
                if (lane == 0) s_orac[w] = bi;
            }
            __syncthreads();
#pragma unroll
            for (int b = 0; b < 8; ++b)
                xp[b] = wte + (size_t)s_orac[b] * DIM;
        }

        float ir[8], iz[8], inn[8], hr[8], hz[8], hn[8];
#pragma unroll
        for (int b = 0; b < 8; ++b) { ir[b]=iz[b]=inn[b]=hr[b]=hz[b]=hn[b]=0.f; }
        for (int k = lane; k < DIM; k += 32) {
            float a0 = wir[k], a1 = wiz[k], a2 = win[k];
            float c0 = whr[k], c1 = whz[k], c2 = whn[k];
#pragma unroll
            for (int b = 0; b < 8; ++b) {
                float xv = xp[b][k];
                float hv = hin[b * DIM + k];
                ir[b]  = fmaf(a0, xv, ir[b]);
                iz[b]  = fmaf(a1, xv, iz[b]);
                inn[b] = fmaf(a2, xv, inn[b]);
                hr[b]  = fmaf(c0, hv, hr[b]);
                hz[b]  = fmaf(c1, hv, hz[b]);
                hn[b]  = fmaf(c2, hv, hn[b]);
            }
        }
#pragma unroll
        for (int b = 0; b < 8; ++b) {
#pragma unroll
            for (int o = 16; o; o >>= 1) {
                ir[b]  += __shfl_xor_sync(0xFFFFFFFFu, ir[b], o);
                iz[b]  += __shfl_xor_sync(0xFFFFFFFFu, iz[b], o);
                inn[b] += __shfl_xor_sync(0xFFFFFFFFu, inn[b], o);
                hr[b]  += __shfl_xor_sync(0xFFFFFFFFu, hr[b], o);
                hz[b]  += __shfl_xor_sync(0xFFFFFFFFu, hz[b], o);
                hn[b]  += __shfl_xor_sync(0xFFFFFFFFu, hn[b], o);
            }
        }
        if (lane < 8) {
            int b = lane;
            float hold = hin[b * DIM + j];
            float r = sigm(ir[b] + bir + hr[b] + bhr);
            float z = sigm(iz[b] + biz + hz[b] + bhz);
            float n = tanhf(inn[b] + bin_ + r * (hn[b] + bhn));
            float hv = (1.f - z) * n + z * hold;
            g_h[t & 1][b * DIM + j] = hv;
            fout[(size_t)(b * TLEN + t) * DIM + j] = hv;
        }
        gbar(gen);
    }
}

// ---------------- misc small kernels ----------------
__global__ void k_gather_cand(const float* __restrict__ wte, float* __restrict__ cand) {
    size_t i = (size_t)blockIdx.x * blockDim.x + threadIdx.x;
    if (i < (size_t)1024 * DIM) {
        int m = (int)(i / DIM), k = (int)(i % DIM);
        unsigned id = 0xFFFFFFFFu - (unsigned)(g_best[m] & 0xFFFFFFFFull);
        cand[i] = wte[(size_t)id * DIM + k];
    }
}

// ---------------- attention: one block per (b,h); thread per query s ----------------
__global__ __launch_bounds__(256) void k_attn(
    const float* __restrict__ q, const float* __restrict__ kk,
    const float* __restrict__ vv, const int* __restrict__ dlen,
    float* __restrict__ ao)
{
    __shared__ float Ks[64][65];
    __shared__ float Vs[64][65];
    int b = blockIdx.x / NHEAD, h = blockIdx.x % NHEAD;
    int s = threadIdx.x;
    int len = dlen[b];

    float qv[HDIM];
    const float* qp = q + ((size_t)(b * SLEN + s)) * DIM + h * HDIM;
#pragma unroll
    for (int d = 0; d < HDIM; ++d) qv[d] = qp[d] * 0.125f;   // 1/sqrt(64)

    float m = -INFINITY, l = 0.f;
    float o[HDIM];
#pragma unroll
    for (int d = 0; d < HDIM; ++d) o[d] = 0.f;

    for (int c = 0; c < 2; ++c) {
        for (int i = threadIdx.x; i < 1024; i += 256) {
            int row = i >> 4, c4 = (i & 15) << 2;
            size_t base = ((size_t)(b * TLEN + c * 64 + row)) * DIM + h * HDIM + c4;
            float4 kvv = *(const float4*)(kk + base);
            float4 vvv = *(const float4*)(vv + base);
            Ks[row][c4 + 0] = kvv.x; Ks[row][c4 + 1] = kvv.y;
            Ks[row][c4 + 2] = kvv.z; Ks[row][c4 + 3] = kvv.w;
            Vs[row][c4 + 0] = vvv.x; Vs[row][c4 + 1] = vvv.y;
            Vs[row][c4 + 2] = vvv.z; Vs[row][c4 + 3] = vvv.w;
        }
        __syncthreads();
        for (int tc = 0; tc < 64; ++tc) {
            int t = c * 64 + tc;
            float sc = 0.f;
#pragma unroll
            for (int d = 0; d < HDIM; ++d) sc = fmaf(qv[d], Ks[tc][d], sc);
            if (t >= len) sc = -1e9f;
            float mn = fmaxf(m, sc);
            float scale = expf(m - mn);       // exp(-inf)=0 on first iteration
            float p = expf(sc - mn);
            l = l * scale + p;
#pragma unroll
            for (int d = 0; d < HDIM; ++d)
                o[d] = o[d] * scale + p * Vs[tc][d];
            m = mn;
        }
        __syncthreads();
    }
    float inv = 1.f / l;
    float* op = ao + ((size_t)(b * SLEN + s)) * DIM + h * HDIM;
#pragma unroll
    for (int d = 0; d < HDIM; ++d) op[d] = o[d] * inv;
}

// ---------------- latent loss (deterministic, fixed partition) ----------------
__global__ void k_loss_part(const float* __restrict__ a, const float* __restrict__ b) {
    __shared__ double red[256];
    int blk = blockIdx.x, tid = threadIdx.x;
    size_t base = (size_t)blk * 3072;
    double s = 0.0;
    for (int i = tid; i < 3072; i += 256) {
        double d = (double)a[base + i] - (double)b[base + i];
        s += d * d;
    }
    red[tid] = s;
    __syncthreads();
    for (int o = 128; o; o >>= 1) {
        if (tid < o) red[tid] += red[tid + o];
        __syncthreads();
    }
    if (tid == 0) g_part[blk] = red[0];
}
__global__ void k_loss_final(float* __restrict__ out) {
    if (threadIdx.x == 0) {
        double s = 0.0;
        for (int i = 0; i < 512; ++i) s += g_part[i];
        out[(size_t)1024 * VOC] = (float)s;
    }
}

// ---------------- host driver ----------------
extern "C" void kernel_launch(void* const* d_in, const int* in_sizes, int n_in,
                              void* d_out, int out_size) {
    const int*   src      = (const int*)d_in[0];
    const int*   src_len  = (const int*)d_in[1];
    const int*   dst      = (const int*)d_in[2];
    const int*   dst_len  = (const int*)d_in[3];
    const float* wte      = (const float*)d_in[4];
    const float* e_wih    = (const float*)d_in[5];
    const float* e_whh    = (const float*)d_in[6];
    const float* e_bih    = (const float*)d_in[7];
    const float* e_bhh    = (const float*)d_in[8];
    const float* d_wih    = (const float*)d_in[9];
    const float* d_whh    = (const float*)d_in[10];
    const float* d_bih    = (const float*)d_in[11];
    const float* d_bhh    = (const float*)d_in[12];
    const float* out_w    = (const float*)d_in[13];
    const float* out_b    = (const float*)d_in[14];
    const float* ll_w     = (const float*)d_in[15];
    const float* ll_b     = (const float*)d_in[16];
    const float* a_inw    = (const float*)d_in[17];
    const float* a_inb    = (const float*)d_in[18];
    const float* a_ow     = (const float*)d_in[19];
    const float* a_ob     = (const float*)d_in[20];
    const float* gumbel   = (const float*)d_in[21];
    float* y = (float*)d_out;

    float* gb = nullptr;    cudaGetSymbolAddress((void**)&gb, g_buf);
    float* hbuf0 = nullptr; cudaGetSymbolAddress((void**)&hbuf0, g_h);
    float* henc = nullptr;  cudaGetSymbolAddress((void**)&henc, g_henc);

    float* src_e  = gb + OFF_SRC_E;
    float* dst_e  = gb + OFF_DST_E;
    float* gi     = gb + OFF_GI;
    float* finalo = gb + OFF_FINAL;
    float* cand   = gb + OFF_CAND;
    float* qb     = gb + OFF_Q;
    float* kb     = gb + OFF_KP;
    float* vb     = gb + OFF_VP;
    float* aob    = gb + OFF_AO;
    float* coutb  = gb + OFF_COUT;
    float* caftb  = gb + OFF_CAFT;
    float* dstout = gb + OFF_DSTOUT;

    // 1) embeddings + best reset
    k_embed<<<9216, 256>>>(src, dst, wte, src_e, dst_e);

    // 2) encoder scan 1 (persistent); h_enc -> g_henc
    k_sgemm_nt<false><<<dim3(18, 16), 256>>>(src_e, e_wih, e_bih, gi, nullptr, 2048, D3, DIM);
    k_gru_scan_p<<<NBLK, 256>>>(gi, e_whh, e_bhh, src_len, nullptr, nullptr, henc, SLEN);

    // 3) scheduled-sampling decode (persistent) -> finalo
    k_decode_p<<<NBLK, 256>>>(dst_e, wte, d_wih, d_whh, d_bih, d_bhh, gumbel, finalo);

    // 4) cand logits + fused argmax; gather cand embeddings
    k_sgemm_nt<true><<<dim3(393, 8), 256>>>(finalo, out_w, out_b, nullptr, nullptr, 1024, VOC, DIM);
    k_gather_cand<<<3072, 256>>>(wte, cand);

    // 5) attention
    k_sgemm_nt<false><<<dim3(6, 16), 256>>>(src_e, a_inw,              a_inb,        qb, nullptr, 2048, DIM, DIM);
    k_sgemm_nt<false><<<dim3(6, 8),  256>>>(cand,  a_inw + 768 * 768,  a_inb + 768,  kb, nullptr, 1024, DIM, DIM);
    k_sgemm_nt<false><<<dim3(6, 8),  256>>>(cand,  a_inw + 1536 * 768, a_inb + 1536, vb, nullptr, 1024, DIM, DIM);
    k_attn<<<96, 256>>>(qb, kb, vb, dst_len, aob);
    k_sgemm_nt<false><<<dim3(6, 16), 256>>>(aob, a_ow, a_ob, coutb, src_e, 2048, DIM, DIM);

    // 6) c_aft + latent loss (c_multi == c_output since PARAM1=0, PARAM2=1)
    k_sgemm_nt<false><<<dim3(6, 16), 256>>>(src_e, ll_w, ll_b, caftb, nullptr, 2048, DIM, DIM);
    k_loss_part<<<512, 256>>>(caftb, coutb);
    k_loss_final<<<1, 32>>>(y);

    // 7) encoder scan 2 on c_output (persistent); final hidden left in g_h[0]
    k_sgemm_nt<false><<<dim3(18, 16), 256>>>(coutb, e_wih, e_bih, gi, nullptr, 2048, D3, DIM);
    k_gru_scan_p<<<NBLK, 256>>>(gi, e_whh, e_bhh, src_len, nullptr, nullptr, nullptr, SLEN);

    // 8) decoder scan (persistent), h0 = g_h[0] (identity re-init), out zero-padded
    k_sgemm_nt<false><<<dim3(18, 8), 256>>>(dst_e, d_wih, d_bih, gi, nullptr, 1024, D3, DIM);
    k_gru_scan_p<<<NBLK, 256>>>(gi, d_whh, d_bhh, dst_len, hbuf0, dstout, nullptr, TLEN);

    // 9) y = dst_out @ out_w^T + out_b
    k_sgemm_nt<false><<<dim3(393, 8), 256>>>(dstout, out_w, out_b, y, nullptr, 1024, VOC, DIM);
}